// round 2
// baseline (speedup 1.0000x reference)
#include <cuda_runtime.h>
#include <cuda_bf16.h>

#define N_NODES 50000
#define N_EDGES 800000
#define IN_NF 21
#define HID 64
#define OUT_NF 20
#define N_LAYERS 4

// ---------------- scratch (device globals; no runtime allocation) -------------
__device__ float g_h[N_NODES * HID];        // node features (current)
__device__ float g_x[N_NODES * 3];          // coordinates (current)
__device__ float g_cnt[N_NODES];            // in-degree (clamped >= 1 at use)
__device__ float g_agg[N_NODES * HID];      // message aggregation
__device__ float g_cagg[N_NODES * 3];       // coord aggregation

__device__ __forceinline__ float silu(float v) {
    return v / (1.0f + __expf(-v));
}

// ---------------- init: copy x, zero cnt --------------------------------------
__global__ void init_kernel(const float* __restrict__ x_in) {
    int i = blockIdx.x * blockDim.x + threadIdx.x;
    if (i < N_NODES * 3) g_x[i] = x_in[i];
    if (i < N_NODES) g_cnt[i] = 0.0f;
}

// ---------------- embedding_in: h = h_in @ W(21x64) + b -----------------------
__global__ void embed_kernel(const float* __restrict__ h_in,
                             const float* __restrict__ W,
                             const float* __restrict__ b) {
    int i = blockIdx.x * blockDim.x + threadIdx.x;
    if (i >= N_NODES * HID) return;
    int n = i >> 6;
    int c = i & 63;
    const float* hr = h_in + n * IN_NF;
    float acc = b[c];
    #pragma unroll
    for (int k = 0; k < IN_NF; k++) acc = fmaf(hr[k], W[k * HID + c], acc);
    g_h[i] = acc;
}

// ---------------- degree count ------------------------------------------------
__global__ void count_kernel(const int* __restrict__ row) {
    int e = blockIdx.x * blockDim.x + threadIdx.x;
    if (e < N_EDGES) atomicAdd(&g_cnt[row[e]], 1.0f);
}

// ---------------- zero aggregation buffers ------------------------------------
__global__ void zero_kernel() {
    int stride = gridDim.x * blockDim.x;
    for (int i = blockIdx.x * blockDim.x + threadIdx.x; i < N_NODES * HID; i += stride)
        g_agg[i] = 0.0f;
    for (int i = blockIdx.x * blockDim.x + threadIdx.x; i < N_NODES * 3; i += stride)
        g_cagg[i] = 0.0f;
}

// ---------------- edge kernel: warp per edge ----------------------------------
// shared layout (floats):
//   W1[129*64]=8256 | W2[4096] | CW1[4096] | B1[64] | B2[64] | CB1[64] | CW2[64]
//   feat[8*132] | m[8*64]
#define E_OFF_W1   0
#define E_OFF_W2   8256
#define E_OFF_CW1  12352
#define E_OFF_B1   16448
#define E_OFF_B2   16512
#define E_OFF_CB1  16576
#define E_OFF_CW2  16640
#define E_OFF_FEAT 16704
#define E_OFF_M    17760
#define E_SMEM_FLOATS 18272

__global__ __launch_bounds__(256) void edge_kernel(
    const int* __restrict__ row, const int* __restrict__ col,
    const float* __restrict__ W1, const float* __restrict__ B1,
    const float* __restrict__ W2, const float* __restrict__ B2,
    const float* __restrict__ CW1, const float* __restrict__ CB1,
    const float* __restrict__ CW2)
{
    extern __shared__ float s[];
    float* sW1  = s + E_OFF_W1;
    float* sW2  = s + E_OFF_W2;
    float* sCW1 = s + E_OFF_CW1;
    float* sB1  = s + E_OFF_B1;
    float* sB2  = s + E_OFF_B2;
    float* sCB1 = s + E_OFF_CB1;
    float* sCW2 = s + E_OFF_CW2;

    int tid = threadIdx.x;
    for (int i = tid; i < 8256; i += 256) sW1[i] = W1[i];
    for (int i = tid; i < 4096; i += 256) { sW2[i] = W2[i]; sCW1[i] = CW1[i]; }
    if (tid < 64) {
        sB1[tid] = B1[tid];
        sB2[tid] = B2[tid];
        sCB1[tid] = CB1[tid];
        sCW2[tid] = CW2[tid];
    }
    __syncthreads();

    int lane  = tid & 31;
    int wloc  = tid >> 5;
    float* fw = s + E_OFF_FEAT + wloc * 132;
    float* mw = s + E_OFF_M + wloc * 64;

    int warp   = (blockIdx.x * blockDim.x + tid) >> 5;
    int nwarps = (gridDim.x * blockDim.x) >> 5;

    for (int e = warp; e < N_EDGES; e += nwarps) {
        int r = row[e];
        int c = col[e];
        const float* hr = g_h + r * HID;
        const float* hc = g_h + c * HID;
        float hr0 = hr[lane], hr1 = hr[32 + lane];
        float hc0 = hc[lane], hc1 = hc[32 + lane];
        float d0 = g_x[r * 3 + 0] - g_x[c * 3 + 0];
        float d1 = g_x[r * 3 + 1] - g_x[c * 3 + 1];
        float d2 = g_x[r * 3 + 2] - g_x[c * 3 + 2];
        float radial = d0 * d0 + d1 * d1 + d2 * d2;

        fw[lane] = hr0; fw[32 + lane] = hr1;
        fw[64 + lane] = hc0; fw[96 + lane] = hc1;
        if (lane == 0) fw[128] = radial;
        __syncwarp();

        // m1 = silu(feat @ W1 + b1)
        float a0 = sB1[lane], a1 = sB1[32 + lane];
        #pragma unroll 8
        for (int k = 0; k < 129; k++) {
            float f = fw[k];
            a0 = fmaf(f, sW1[k * 64 + lane], a0);
            a1 = fmaf(f, sW1[k * 64 + 32 + lane], a1);
        }
        a0 = silu(a0); a1 = silu(a1);
        __syncwarp();
        mw[lane] = a0; mw[32 + lane] = a1;
        __syncwarp();

        // m = silu(m1 @ W2 + b2)
        float b0 = sB2[lane], b1 = sB2[32 + lane];
        #pragma unroll 8
        for (int k = 0; k < 64; k++) {
            float f = mw[k];
            b0 = fmaf(f, sW2[k * 64 + lane], b0);
            b1 = fmaf(f, sW2[k * 64 + 32 + lane], b1);
        }
        float m0 = silu(b0), m1 = silu(b1);
        __syncwarp();
        mw[lane] = m0; mw[32 + lane] = m1;
        __syncwarp();

        // cmid = silu(m @ CW1 + cb1)
        float c0 = sCB1[lane], c1 = sCB1[32 + lane];
        #pragma unroll 8
        for (int k = 0; k < 64; k++) {
            float f = mw[k];
            c0 = fmaf(f, sCW1[k * 64 + lane], c0);
            c1 = fmaf(f, sCW1[k * 64 + 32 + lane], c1);
        }
        c0 = silu(c0); c1 = silu(c1);

        // scalar = cmid @ CW2  (H -> 1)
        float sc = c0 * sCW2[lane] + c1 * sCW2[32 + lane];
        #pragma unroll
        for (int o = 16; o; o >>= 1) sc += __shfl_xor_sync(0xFFFFFFFFu, sc, o);

        // scatter
        atomicAdd(&g_agg[r * HID + lane], m0);
        atomicAdd(&g_agg[r * HID + 32 + lane], m1);
        if (lane < 3) {
            float dd = (lane == 0) ? d0 : ((lane == 1) ? d1 : d2);
            atomicAdd(&g_cagg[r * 3 + lane], dd * sc);
        }
    }
}

// ---------------- node kernel: warp per node ----------------------------------
// shared: W1[128*64]=8192 | W2[4096] | B1[64] | B2[64] | feat[8*128] | u[8*64]
#define N_OFF_W1   0
#define N_OFF_W2   8192
#define N_OFF_B1   12288
#define N_OFF_B2   12352
#define N_OFF_FEAT 12416
#define N_OFF_U    13440
#define N_SMEM_FLOATS 13952

__global__ __launch_bounds__(256) void node_kernel(
    const float* __restrict__ W1, const float* __restrict__ B1,
    const float* __restrict__ W2, const float* __restrict__ B2)
{
    extern __shared__ float s[];
    float* sW1 = s + N_OFF_W1;
    float* sW2 = s + N_OFF_W2;
    float* sB1 = s + N_OFF_B1;
    float* sB2 = s + N_OFF_B2;

    int tid = threadIdx.x;
    for (int i = tid; i < 8192; i += 256) sW1[i] = W1[i];
    for (int i = tid; i < 4096; i += 256) sW2[i] = W2[i];
    if (tid < 64) { sB1[tid] = B1[tid]; sB2[tid] = B2[tid]; }
    __syncthreads();

    int lane = tid & 31;
    int wloc = tid >> 5;
    float* fw = s + N_OFF_FEAT + wloc * 128;
    float* uw = s + N_OFF_U + wloc * 64;

    int warp   = (blockIdx.x * blockDim.x + tid) >> 5;
    int nwarps = (gridDim.x * blockDim.x) >> 5;

    for (int n = warp; n < N_NODES; n += nwarps) {
        float h0 = g_h[n * HID + lane], h1 = g_h[n * HID + 32 + lane];
        float a0 = g_agg[n * HID + lane], a1 = g_agg[n * HID + 32 + lane];
        fw[lane] = h0; fw[32 + lane] = h1;
        fw[64 + lane] = a0; fw[96 + lane] = a1;
        __syncwarp();

        float u0 = sB1[lane], u1 = sB1[32 + lane];
        #pragma unroll 8
        for (int k = 0; k < 128; k++) {
            float f = fw[k];
            u0 = fmaf(f, sW1[k * 64 + lane], u0);
            u1 = fmaf(f, sW1[k * 64 + 32 + lane], u1);
        }
        u0 = silu(u0); u1 = silu(u1);
        __syncwarp();
        uw[lane] = u0; uw[32 + lane] = u1;
        __syncwarp();

        float o0 = sB2[lane], o1 = sB2[32 + lane];
        #pragma unroll 8
        for (int k = 0; k < 64; k++) {
            float f = uw[k];
            o0 = fmaf(f, sW2[k * 64 + lane], o0);
            o1 = fmaf(f, sW2[k * 64 + 32 + lane], o1);
        }
        g_h[n * HID + lane] = h0 + o0;
        g_h[n * HID + 32 + lane] = h1 + o1;

        if (lane < 3) {
            float cnt = g_cnt[n];
            if (cnt < 1.0f) cnt = 1.0f;
            g_x[n * 3 + lane] += g_cagg[n * 3 + lane] / cnt;
        }
        __syncwarp();
    }
}

// ---------------- head: out = relu((h@EW+eb)@HW1+hb1)@HW2+hb2 -----------------
// shared: EW[4096] | HW1[4096] | HW2[64*20]=1280 | EB[64] | HB1[64] | HB2[20] | feat[8*64]
#define H_OFF_EW   0
#define H_OFF_HW1  4096
#define H_OFF_HW2  8192
#define H_OFF_EB   9472
#define H_OFF_HB1  9536
#define H_OFF_HB2  9600
#define H_OFF_FEAT 9620
#define H_SMEM_FLOATS 10132

__global__ __launch_bounds__(256) void head_kernel(
    const float* __restrict__ EW, const float* __restrict__ EB,
    const float* __restrict__ HW1, const float* __restrict__ HB1,
    const float* __restrict__ HW2, const float* __restrict__ HB2,
    float* __restrict__ out)
{
    extern __shared__ float s[];
    float* sEW  = s + H_OFF_EW;
    float* sHW1 = s + H_OFF_HW1;
    float* sHW2 = s + H_OFF_HW2;
    float* sEB  = s + H_OFF_EB;
    float* sHB1 = s + H_OFF_HB1;
    float* sHB2 = s + H_OFF_HB2;

    int tid = threadIdx.x;
    for (int i = tid; i < 4096; i += 256) { sEW[i] = EW[i]; sHW1[i] = HW1[i]; }
    for (int i = tid; i < 1280; i += 256) sHW2[i] = HW2[i];
    if (tid < 64) { sEB[tid] = EB[tid]; sHB1[tid] = HB1[tid]; }
    if (tid < 20) sHB2[tid] = HB2[tid];
    __syncthreads();

    int lane = tid & 31;
    int wloc = tid >> 5;
    float* fw = s + H_OFF_FEAT + wloc * 64;

    int warp   = (blockIdx.x * blockDim.x + tid) >> 5;
    int nwarps = (gridDim.x * blockDim.x) >> 5;

    for (int n = warp; n < N_NODES; n += nwarps) {
        float h0 = g_h[n * HID + lane], h1 = g_h[n * HID + 32 + lane];
        fw[lane] = h0; fw[32 + lane] = h1;
        __syncwarp();

        // t = h @ EW + eb
        float t0 = sEB[lane], t1 = sEB[32 + lane];
        #pragma unroll 8
        for (int k = 0; k < 64; k++) {
            float f = fw[k];
            t0 = fmaf(f, sEW[k * 64 + lane], t0);
            t1 = fmaf(f, sEW[k * 64 + 32 + lane], t1);
        }
        __syncwarp();
        fw[lane] = t0; fw[32 + lane] = t1;
        __syncwarp();

        // r = relu(t @ HW1 + hb1)
        float r0 = sHB1[lane], r1 = sHB1[32 + lane];
        #pragma unroll 8
        for (int k = 0; k < 64; k++) {
            float f = fw[k];
            r0 = fmaf(f, sHW1[k * 64 + lane], r0);
            r1 = fmaf(f, sHW1[k * 64 + 32 + lane], r1);
        }
        r0 = fmaxf(r0, 0.0f); r1 = fmaxf(r1, 0.0f);
        __syncwarp();
        fw[lane] = r0; fw[32 + lane] = r1;
        __syncwarp();

        // out = r @ HW2 + hb2   (64 -> 20)
        if (lane < OUT_NF) {
            float o = sHB2[lane];
            #pragma unroll 8
            for (int k = 0; k < 64; k++)
                o = fmaf(fw[k], sHW2[k * OUT_NF + lane], o);
            out[n * OUT_NF + lane] = o;
        }
        __syncwarp();
    }
}

// ---------------- launcher ----------------------------------------------------
extern "C" void kernel_launch(void* const* d_in, const int* in_sizes, int n_in,
                              void* d_out, int out_size) {
    const float* h_in     = (const float*)d_in[0];
    const float* x_in     = (const float*)d_in[1];
    const int*   edges    = (const int*)d_in[2];
    const float* emb_in_w = (const float*)d_in[3];
    const float* emb_in_b = (const float*)d_in[4];
    const float* emb_out_w= (const float*)d_in[5];
    const float* emb_out_b= (const float*)d_in[6];
    const float* edge_w1  = (const float*)d_in[7];
    const float* edge_b1  = (const float*)d_in[8];
    const float* edge_w2  = (const float*)d_in[9];
    const float* edge_b2  = (const float*)d_in[10];
    const float* node_w1  = (const float*)d_in[11];
    const float* node_b1  = (const float*)d_in[12];
    const float* node_w2  = (const float*)d_in[13];
    const float* node_b2  = (const float*)d_in[14];
    const float* coord_w1 = (const float*)d_in[15];
    const float* coord_b1 = (const float*)d_in[16];
    const float* coord_w2 = (const float*)d_in[17];
    const float* head_w1  = (const float*)d_in[18];
    const float* head_b1  = (const float*)d_in[19];
    const float* head_w2  = (const float*)d_in[20];
    const float* head_b2  = (const float*)d_in[21];
    float* out = (float*)d_out;

    cudaFuncSetAttribute(edge_kernel, cudaFuncAttributeMaxDynamicSharedMemorySize,
                         E_SMEM_FLOATS * sizeof(float));
    cudaFuncSetAttribute(node_kernel, cudaFuncAttributeMaxDynamicSharedMemorySize,
                         N_SMEM_FLOATS * sizeof(float));
    cudaFuncSetAttribute(head_kernel, cudaFuncAttributeMaxDynamicSharedMemorySize,
                         H_SMEM_FLOATS * sizeof(float));

    const int* row = edges;
    const int* col = edges + N_EDGES;

    init_kernel<<<(N_NODES * 3 + 255) / 256, 256>>>(x_in);
    embed_kernel<<<(N_NODES * HID + 255) / 256, 256>>>(h_in, emb_in_w, emb_in_b);
    count_kernel<<<(N_EDGES + 255) / 256, 256>>>(row);

    for (int l = 0; l < N_LAYERS; l++) {
        zero_kernel<<<2048, 256>>>();
        edge_kernel<<<444, 256, E_SMEM_FLOATS * sizeof(float)>>>(
            row, col,
            edge_w1 + l * (2 * HID + 1) * HID, edge_b1 + l * HID,
            edge_w2 + l * HID * HID, edge_b2 + l * HID,
            coord_w1 + l * HID * HID, coord_b1 + l * HID,
            coord_w2 + l * HID);
        node_kernel<<<6250, 256, N_SMEM_FLOATS * sizeof(float)>>>(
            node_w1 + l * 2 * HID * HID, node_b1 + l * HID,
            node_w2 + l * HID * HID, node_b2 + l * HID);
    }

    head_kernel<<<6250, 256, H_SMEM_FLOATS * sizeof(float)>>>(
        emb_out_w, emb_out_b, head_w1, head_b1, head_w2, head_b2, out);
}

// round 3
// speedup vs baseline: 2.4208x; 2.4208x over previous
#include <cuda_runtime.h>
#include <cuda_bf16.h>

#define N_NODES 50000
#define N_EDGES 800000
#define IN_NF 21
#define HID 64
#define OUT_NF 20
#define N_LAYERS 4

#define EPW 8            // edges (or nodes) per warp
#define CTA_THREADS 512
#define WARPS_CTA 16
#define TILE_E (EPW * WARPS_CTA)          // 128
#define EDGE_TILES (N_EDGES / TILE_E)     // 6250 exact
#define NODE_TILES ((N_NODES + TILE_E - 1) / TILE_E)  // 391
#define GRID_PERSIST 152

// ---------------- scratch (device globals; no runtime allocation) -------------
__device__ float g_h[N_NODES * HID];
__device__ float g_x[N_NODES * 3];
__device__ float g_cnt[N_NODES];
__device__ float g_agg[N_NODES * HID];
__device__ float g_cagg[N_NODES * 3];

__device__ __forceinline__ float silu(float v) {
    return v / (1.0f + __expf(-v));
}

// Shared register-blocked GEMM: 8 rows (edges/nodes) x 64 outputs per warp.
// W: [K x 64] row-major in smem. src: per-warp tile, row-major with STRIDE floats
// per row (STRIDE multiple of 4; base 16B aligned). Each lane owns outputs
// (2*lane, 2*lane+1). Feature reads are warp-uniform broadcasts.
template<int K, int STRIDE>
__device__ __forceinline__ void gemm_acc(float2 acc[EPW], const float* __restrict__ W,
                                         const float* __restrict__ src, int lane) {
    #pragma unroll 4
    for (int k = 0; k < K; k += 4) {
        float2 w0 = ((const float2*)(W + (k + 0) * 64))[lane];
        float2 w1 = ((const float2*)(W + (k + 1) * 64))[lane];
        float2 w2 = ((const float2*)(W + (k + 2) * 64))[lane];
        float2 w3 = ((const float2*)(W + (k + 3) * 64))[lane];
        #pragma unroll
        for (int e = 0; e < EPW; e++) {
            float4 f = *(const float4*)(src + e * STRIDE + k);
            acc[e].x = fmaf(f.x, w0.x, acc[e].x); acc[e].y = fmaf(f.x, w0.y, acc[e].y);
            acc[e].x = fmaf(f.y, w1.x, acc[e].x); acc[e].y = fmaf(f.y, w1.y, acc[e].y);
            acc[e].x = fmaf(f.z, w2.x, acc[e].x); acc[e].y = fmaf(f.z, w2.y, acc[e].y);
            acc[e].x = fmaf(f.w, w3.x, acc[e].x); acc[e].y = fmaf(f.w, w3.y, acc[e].y);
        }
    }
}

// ---------------- init: copy x, zero cnt --------------------------------------
__global__ void init_kernel(const float* __restrict__ x_in) {
    int i = blockIdx.x * blockDim.x + threadIdx.x;
    if (i < N_NODES * 3) g_x[i] = x_in[i];
    if (i < N_NODES) g_cnt[i] = 0.0f;
}

// ---------------- embedding_in ------------------------------------------------
__global__ void embed_kernel(const float* __restrict__ h_in,
                             const float* __restrict__ W,
                             const float* __restrict__ b) {
    int i = blockIdx.x * blockDim.x + threadIdx.x;
    if (i >= N_NODES * HID) return;
    int n = i >> 6;
    int c = i & 63;
    const float* hr = h_in + n * IN_NF;
    float acc = b[c];
    #pragma unroll
    for (int k = 0; k < IN_NF; k++) acc = fmaf(hr[k], W[k * HID + c], acc);
    g_h[i] = acc;
}

// ---------------- degree count ------------------------------------------------
__global__ void count_kernel(const int* __restrict__ row) {
    int e = blockIdx.x * blockDim.x + threadIdx.x;
    if (e < N_EDGES) atomicAdd(&g_cnt[row[e]], 1.0f);
}

// ---------------- zero aggregation buffers ------------------------------------
__global__ void zero_kernel() {
    int stride = gridDim.x * blockDim.x;
    for (int i = blockIdx.x * blockDim.x + threadIdx.x; i < N_NODES * HID; i += stride)
        g_agg[i] = 0.0f;
    for (int i = blockIdx.x * blockDim.x + threadIdx.x; i < N_NODES * 3; i += stride)
        g_cagg[i] = 0.0f;
}

// ---------------- edge kernel: 8 edges per warp, persistent -------------------
// smem (floats): W1[129*64]=8256 | W2[4096] | CW1[4096] | B1,B2,CB1,CW2[64 ea]
//                feat[16 warps * 8 edges * 136] | m[16 * 8 * 64]
#define E_OFF_W1   0
#define E_OFF_W2   8256
#define E_OFF_CW1  12352
#define E_OFF_B1   16448
#define E_OFF_B2   16512
#define E_OFF_CB1  16576
#define E_OFF_CW2  16640
#define E_OFF_FEAT 16704
#define E_FEAT_STRIDE 136
#define E_OFF_M    (E_OFF_FEAT + WARPS_CTA * EPW * E_FEAT_STRIDE)   // 34112
#define E_SMEM_FLOATS (E_OFF_M + WARPS_CTA * EPW * 64)              // 42304

__global__ __launch_bounds__(CTA_THREADS, 1) void edge_kernel(
    const int* __restrict__ row, const int* __restrict__ col,
    const float* __restrict__ W1, const float* __restrict__ B1,
    const float* __restrict__ W2, const float* __restrict__ B2,
    const float* __restrict__ CW1, const float* __restrict__ CB1,
    const float* __restrict__ CW2)
{
    extern __shared__ float s[];
    float* sW1  = s + E_OFF_W1;
    float* sW2  = s + E_OFF_W2;
    float* sCW1 = s + E_OFF_CW1;
    float* sB1  = s + E_OFF_B1;
    float* sB2  = s + E_OFF_B2;
    float* sCB1 = s + E_OFF_CB1;
    float* sCW2 = s + E_OFF_CW2;

    int tid = threadIdx.x;
    for (int i = tid; i < 8256; i += CTA_THREADS) sW1[i] = W1[i];
    for (int i = tid; i < 4096; i += CTA_THREADS) { sW2[i] = W2[i]; sCW1[i] = CW1[i]; }
    if (tid < 64) {
        sB1[tid] = B1[tid]; sB2[tid] = B2[tid];
        sCB1[tid] = CB1[tid]; sCW2[tid] = CW2[tid];
    }
    __syncthreads();

    int lane = tid & 31;
    int wid  = tid >> 5;
    float* fw = s + E_OFF_FEAT + wid * (EPW * E_FEAT_STRIDE);
    float* mw = s + E_OFF_M    + wid * (EPW * 64);

    for (int tile = blockIdx.x; tile < EDGE_TILES; tile += gridDim.x) {
        int ebase = tile * TILE_E + wid * EPW;
        int r[EPW];

        // ---- gather: h[row], h[col], diff/radial ----
        #pragma unroll
        for (int e = 0; e < EPW; e++) {
            int rr = __ldg(&row[ebase + e]);
            int cc = __ldg(&col[ebase + e]);
            r[e] = rr;
            float2 hr = __ldg((const float2*)(g_h + rr * HID) + lane);
            float2 hc = __ldg((const float2*)(g_h + cc * HID) + lane);
            ((float2*)(fw + e * E_FEAT_STRIDE))[lane] = hr;
            ((float2*)(fw + e * E_FEAT_STRIDE + 64))[lane] = hc;
            float d0 = g_x[rr * 3 + 0] - g_x[cc * 3 + 0];
            float d1 = g_x[rr * 3 + 1] - g_x[cc * 3 + 1];
            float d2 = g_x[rr * 3 + 2] - g_x[cc * 3 + 2];
            if (lane == 0) {
                fw[e * E_FEAT_STRIDE + 128] = d0 * d0 + d1 * d1 + d2 * d2;
                fw[e * E_FEAT_STRIDE + 129] = d0;
                fw[e * E_FEAT_STRIDE + 130] = d1;
                fw[e * E_FEAT_STRIDE + 131] = d2;
            }
        }
        __syncwarp();

        // ---- GEMM1: m1 = silu(feat @ W1 + b1); radial folded into init ----
        float2 acc[EPW];
        {
            float2 bv   = ((const float2*)sB1)[lane];
            float2 w128 = ((const float2*)(sW1 + 128 * 64))[lane];
            #pragma unroll
            for (int e = 0; e < EPW; e++) {
                float rad = fw[e * E_FEAT_STRIDE + 128];
                acc[e].x = fmaf(rad, w128.x, bv.x);
                acc[e].y = fmaf(rad, w128.y, bv.y);
            }
        }
        gemm_acc<128, E_FEAT_STRIDE>(acc, sW1, fw, lane);
        #pragma unroll
        for (int e = 0; e < EPW; e++)
            ((float2*)(mw + e * 64))[lane] = make_float2(silu(acc[e].x), silu(acc[e].y));
        __syncwarp();

        // ---- GEMM2: m = silu(m1 @ W2 + b2) ----
        {
            float2 bv = ((const float2*)sB2)[lane];
            #pragma unroll
            for (int e = 0; e < EPW; e++) acc[e] = bv;
        }
        gemm_acc<64, 64>(acc, sW2, mw, lane);
        #pragma unroll
        for (int e = 0; e < EPW; e++) {
            acc[e].x = silu(acc[e].x);
            acc[e].y = silu(acc[e].y);
        }
        __syncwarp();   // all lanes done reading m1 before overwrite
        #pragma unroll
        for (int e = 0; e < EPW; e++) {
            ((float2*)(mw + e * 64))[lane] = acc[e];
            atomicAdd(&g_agg[r[e] * HID + 2 * lane],     acc[e].x);
            atomicAdd(&g_agg[r[e] * HID + 2 * lane + 1], acc[e].y);
        }
        __syncwarp();

        // ---- GEMM3: cmid = silu(m @ CW1 + cb1); sc = cmid @ CW2 ----
        {
            float2 bv = ((const float2*)sCB1)[lane];
            #pragma unroll
            for (int e = 0; e < EPW; e++) acc[e] = bv;
        }
        gemm_acc<64, 64>(acc, sCW1, mw, lane);
        float2 cw2 = ((const float2*)sCW2)[lane];
        #pragma unroll
        for (int e = 0; e < EPW; e++) {
            float p = silu(acc[e].x) * cw2.x + silu(acc[e].y) * cw2.y;
            #pragma unroll
            for (int o = 16; o; o >>= 1) p += __shfl_xor_sync(0xFFFFFFFFu, p, o);
            if (lane < 3) {
                float d = fw[e * E_FEAT_STRIDE + 129 + lane];
                atomicAdd(&g_cagg[r[e] * 3 + lane], d * p);
            }
        }
        __syncwarp();   // before next tile reuses fw
    }
}

// ---------------- node kernel: 8 nodes per warp, persistent -------------------
// smem: W1[128*64]=8192 | W2[4096] | B1[64] | B2[64] | feat[16*8*128] | u[16*8*64]
#define N_OFF_W1   0
#define N_OFF_W2   8192
#define N_OFF_B1   12288
#define N_OFF_B2   12352
#define N_OFF_FEAT 12416
#define N_FEAT_STRIDE 128
#define N_OFF_U    (N_OFF_FEAT + WARPS_CTA * EPW * N_FEAT_STRIDE)   // 28800
#define N_SMEM_FLOATS (N_OFF_U + WARPS_CTA * EPW * 64)              // 36992

__global__ __launch_bounds__(CTA_THREADS, 1) void node_kernel(
    const float* __restrict__ W1, const float* __restrict__ B1,
    const float* __restrict__ W2, const float* __restrict__ B2)
{
    extern __shared__ float s[];
    float* sW1 = s + N_OFF_W1;
    float* sW2 = s + N_OFF_W2;
    float* sB1 = s + N_OFF_B1;
    float* sB2 = s + N_OFF_B2;

    int tid = threadIdx.x;
    for (int i = tid; i < 8192; i += CTA_THREADS) sW1[i] = W1[i];
    for (int i = tid; i < 4096; i += CTA_THREADS) sW2[i] = W2[i];
    if (tid < 64) { sB1[tid] = B1[tid]; sB2[tid] = B2[tid]; }
    __syncthreads();

    int lane = tid & 31;
    int wid  = tid >> 5;
    float* fw = s + N_OFF_FEAT + wid * (EPW * N_FEAT_STRIDE);
    float* uw = s + N_OFF_U    + wid * (EPW * 64);

    for (int tile = blockIdx.x; tile < NODE_TILES; tile += gridDim.x) {
        int nbase = tile * TILE_E + wid * EPW;

        #pragma unroll
        for (int e = 0; e < EPW; e++) {
            int n = nbase + e;
            if (n < N_NODES) {
                float2 hv = ((const float2*)(g_h   + n * HID))[lane];
                float2 av = ((const float2*)(g_agg + n * HID))[lane];
                ((float2*)(fw + e * N_FEAT_STRIDE))[lane] = hv;
                ((float2*)(fw + e * N_FEAT_STRIDE + 64))[lane] = av;
            }
        }
        __syncwarp();

        float2 acc[EPW];
        {
            float2 bv = ((const float2*)sB1)[lane];
            #pragma unroll
            for (int e = 0; e < EPW; e++) acc[e] = bv;
        }
        gemm_acc<128, N_FEAT_STRIDE>(acc, sW1, fw, lane);
        #pragma unroll
        for (int e = 0; e < EPW; e++)
            ((float2*)(uw + e * 64))[lane] = make_float2(silu(acc[e].x), silu(acc[e].y));
        __syncwarp();

        {
            float2 bv = ((const float2*)sB2)[lane];
            #pragma unroll
            for (int e = 0; e < EPW; e++) acc[e] = bv;
        }
        gemm_acc<64, 64>(acc, sW2, uw, lane);

        #pragma unroll
        for (int e = 0; e < EPW; e++) {
            int n = nbase + e;
            if (n < N_NODES) {
                float2 hv = ((const float2*)(fw + e * N_FEAT_STRIDE))[lane];
                ((float2*)(g_h + n * HID))[lane] =
                    make_float2(hv.x + acc[e].x, hv.y + acc[e].y);
                if (lane < 3) {
                    float cnt = g_cnt[n];
                    if (cnt < 1.0f) cnt = 1.0f;
                    g_x[n * 3 + lane] += g_cagg[n * 3 + lane] / cnt;
                }
            }
        }
        __syncwarp();
    }
}

// ---------------- head: out = relu((h@EW+eb)@HW1+hb1)@HW2+hb2 -----------------
#define H_OFF_EW   0
#define H_OFF_HW1  4096
#define H_OFF_HW2  8192
#define H_OFF_EB   9472
#define H_OFF_HB1  9536
#define H_OFF_HB2  9600
#define H_OFF_FEAT 9620
#define H_SMEM_FLOATS 10132

__global__ __launch_bounds__(256) void head_kernel(
    const float* __restrict__ EW, const float* __restrict__ EB,
    const float* __restrict__ HW1, const float* __restrict__ HB1,
    const float* __restrict__ HW2, const float* __restrict__ HB2,
    float* __restrict__ out)
{
    extern __shared__ float s[];
    float* sEW  = s + H_OFF_EW;
    float* sHW1 = s + H_OFF_HW1;
    float* sHW2 = s + H_OFF_HW2;
    float* sEB  = s + H_OFF_EB;
    float* sHB1 = s + H_OFF_HB1;
    float* sHB2 = s + H_OFF_HB2;

    int tid = threadIdx.x;
    for (int i = tid; i < 4096; i += 256) { sEW[i] = EW[i]; sHW1[i] = HW1[i]; }
    for (int i = tid; i < 1280; i += 256) sHW2[i] = HW2[i];
    if (tid < 64) { sEB[tid] = EB[tid]; sHB1[tid] = HB1[tid]; }
    if (tid < 20) sHB2[tid] = HB2[tid];
    __syncthreads();

    int lane = tid & 31;
    int wloc = tid >> 5;
    float* fw = s + H_OFF_FEAT + wloc * 64;

    int warp   = (blockIdx.x * blockDim.x + tid) >> 5;
    int nwarps = (gridDim.x * blockDim.x) >> 5;

    for (int n = warp; n < N_NODES; n += nwarps) {
        float h0 = g_h[n * HID + lane], h1 = g_h[n * HID + 32 + lane];
        fw[lane] = h0; fw[32 + lane] = h1;
        __syncwarp();

        float t0 = sEB[lane], t1 = sEB[32 + lane];
        #pragma unroll 8
        for (int k = 0; k < 64; k++) {
            float f = fw[k];
            t0 = fmaf(f, sEW[k * 64 + lane], t0);
            t1 = fmaf(f, sEW[k * 64 + 32 + lane], t1);
        }
        __syncwarp();
        fw[lane] = t0; fw[32 + lane] = t1;
        __syncwarp();

        float r0 = sHB1[lane], r1 = sHB1[32 + lane];
        #pragma unroll 8
        for (int k = 0; k < 64; k++) {
            float f = fw[k];
            r0 = fmaf(f, sHW1[k * 64 + lane], r0);
            r1 = fmaf(f, sHW1[k * 64 + 32 + lane], r1);
        }
        r0 = fmaxf(r0, 0.0f); r1 = fmaxf(r1, 0.0f);
        __syncwarp();
        fw[lane] = r0; fw[32 + lane] = r1;
        __syncwarp();

        if (lane < OUT_NF) {
            float o = sHB2[lane];
            #pragma unroll 8
            for (int k = 0; k < 64; k++)
                o = fmaf(fw[k], sHW2[k * OUT_NF + lane], o);
            out[n * OUT_NF + lane] = o;
        }
        __syncwarp();
    }
}

// ---------------- launcher ----------------------------------------------------
extern "C" void kernel_launch(void* const* d_in, const int* in_sizes, int n_in,
                              void* d_out, int out_size) {
    const float* h_in      = (const float*)d_in[0];
    const float* x_in      = (const float*)d_in[1];
    const int*   edges     = (const int*)d_in[2];
    const float* emb_in_w  = (const float*)d_in[3];
    const float* emb_in_b  = (const float*)d_in[4];
    const float* emb_out_w = (const float*)d_in[5];
    const float* emb_out_b = (const float*)d_in[6];
    const float* edge_w1   = (const float*)d_in[7];
    const float* edge_b1   = (const float*)d_in[8];
    const float* edge_w2   = (const float*)d_in[9];
    const float* edge_b2   = (const float*)d_in[10];
    const float* node_w1   = (const float*)d_in[11];
    const float* node_b1   = (const float*)d_in[12];
    const float* node_w2   = (const float*)d_in[13];
    const float* node_b2   = (const float*)d_in[14];
    const float* coord_w1  = (const float*)d_in[15];
    const float* coord_b1  = (const float*)d_in[16];
    const float* coord_w2  = (const float*)d_in[17];
    const float* head_w1   = (const float*)d_in[18];
    const float* head_b1   = (const float*)d_in[19];
    const float* head_w2   = (const float*)d_in[20];
    const float* head_b2   = (const float*)d_in[21];
    float* out = (float*)d_out;

    cudaFuncSetAttribute(edge_kernel, cudaFuncAttributeMaxDynamicSharedMemorySize,
                         E_SMEM_FLOATS * sizeof(float));
    cudaFuncSetAttribute(node_kernel, cudaFuncAttributeMaxDynamicSharedMemorySize,
                         N_SMEM_FLOATS * sizeof(float));
    cudaFuncSetAttribute(head_kernel, cudaFuncAttributeMaxDynamicSharedMemorySize,
                         H_SMEM_FLOATS * sizeof(float));

    const int* row = edges;
    const int* col = edges + N_EDGES;

    init_kernel<<<(N_NODES * 3 + 255) / 256, 256>>>(x_in);
    embed_kernel<<<(N_NODES * HID + 255) / 256, 256>>>(h_in, emb_in_w, emb_in_b);
    count_kernel<<<(N_EDGES + 255) / 256, 256>>>(row);

    for (int l = 0; l < N_LAYERS; l++) {
        zero_kernel<<<2048, 256>>>();
        edge_kernel<<<GRID_PERSIST, CTA_THREADS, E_SMEM_FLOATS * sizeof(float)>>>(
            row, col,
            edge_w1 + l * (2 * HID + 1) * HID, edge_b1 + l * HID,
            edge_w2 + l * HID * HID, edge_b2 + l * HID,
            coord_w1 + l * HID * HID, coord_b1 + l * HID,
            coord_w2 + l * HID);
        node_kernel<<<GRID_PERSIST, CTA_THREADS, N_SMEM_FLOATS * sizeof(float)>>>(
            node_w1 + l * 2 * HID * HID, node_b1 + l * HID,
            node_w2 + l * HID * HID, node_b2 + l * HID);
    }

    head_kernel<<<6250, 256, H_SMEM_FLOATS * sizeof(float)>>>(
        emb_out_w, emb_out_b, head_w1, head_b1, head_w2, head_b2, out);
}

// round 4
// speedup vs baseline: 2.7304x; 1.1279x over previous
#include <cuda_runtime.h>
#include <cuda_bf16.h>

#define N_NODES 50000
#define N_EDGES 800000
#define IN_NF 21
#define HID 64
#define OUT_NF 20
#define N_LAYERS 4

#define EPW 8            // edges (or nodes) per warp (= 4 pairs)
#define CTA_THREADS 512
#define WARPS_CTA 16
#define TILE_E (EPW * WARPS_CTA)          // 128
#define EDGE_TILES (N_EDGES / TILE_E)     // 6250 exact
#define NODE_TILES ((N_NODES + TILE_E - 1) / TILE_E)  // 391
#define GRID_PERSIST 152

typedef unsigned long long ull;
union F2u { ull u; float2 f; };

__device__ __forceinline__ ull splat2(float v) {
    ull r; asm("mov.b64 %0, {%1, %1};" : "=l"(r) : "f"(v)); return r;
}
__device__ __forceinline__ void ffma2(ull& a, ull x, ull y) {
    asm("fma.rn.f32x2 %0, %1, %2, %0;" : "+l"(a) : "l"(x), "l"(y));
}

// ---------------- scratch (device globals; no runtime allocation) -------------
__device__ float g_h[N_NODES * HID];
__device__ float g_x[N_NODES * 3];
__device__ float g_cnt[N_NODES];
__device__ float g_agg[N_NODES * HID];
__device__ float g_cagg[N_NODES * 3];

__device__ __forceinline__ float silu(float v) {
    return v / (1.0f + __expf(-v));
}

// Pair-packed register GEMM: 4 edge-pairs x 64 outputs per warp.
// W: [K x 64] row-major smem. fp: pair-major features, pair p at fp + p*STRIDE,
// slot for k is float2 {f_even[k], f_odd[k]} at offset 2*k. Lane owns outputs
// (2*lane, 2*lane+1); acc[p][j] = {out for even edge, out for odd edge}.
template<int K, int STRIDE>
__device__ __forceinline__ void gemm_pair(ull acc[4][2], const float* __restrict__ W,
                                          const float* __restrict__ fp, int lane) {
    #pragma unroll 4
    for (int k = 0; k < K; k += 2) {
        float2 w0 = ((const float2*)(W + k * 64))[lane];
        float2 w1 = ((const float2*)(W + (k + 1) * 64))[lane];
        ull w00 = splat2(w0.x), w01 = splat2(w0.y);
        ull w10 = splat2(w1.x), w11 = splat2(w1.y);
        #pragma unroll
        for (int p = 0; p < 4; p++) {
            ulonglong2 f = *(const ulonglong2*)(fp + p * STRIDE + 2 * k);
            ffma2(acc[p][0], f.x, w00);
            ffma2(acc[p][1], f.x, w01);
            ffma2(acc[p][0], f.y, w10);
            ffma2(acc[p][1], f.y, w11);
        }
    }
}

// ---------------- init: copy x, zero cnt --------------------------------------
__global__ void init_kernel(const float* __restrict__ x_in) {
    int i = blockIdx.x * blockDim.x + threadIdx.x;
    if (i < N_NODES * 3) g_x[i] = x_in[i];
    if (i < N_NODES) g_cnt[i] = 0.0f;
}

// ---------------- embedding_in ------------------------------------------------
__global__ void embed_kernel(const float* __restrict__ h_in,
                             const float* __restrict__ W,
                             const float* __restrict__ b) {
    int i = blockIdx.x * blockDim.x + threadIdx.x;
    if (i >= N_NODES * HID) return;
    int n = i >> 6;
    int c = i & 63;
    const float* hr = h_in + n * IN_NF;
    float acc = b[c];
    #pragma unroll
    for (int k = 0; k < IN_NF; k++) acc = fmaf(hr[k], W[k * HID + c], acc);
    g_h[i] = acc;
}

// ---------------- degree count ------------------------------------------------
__global__ void count_kernel(const int* __restrict__ row) {
    int e = blockIdx.x * blockDim.x + threadIdx.x;
    if (e < N_EDGES) atomicAdd(&g_cnt[row[e]], 1.0f);
}

// ---------------- zero aggregation buffers ------------------------------------
__global__ void zero_kernel() {
    int stride = gridDim.x * blockDim.x;
    for (int i = blockIdx.x * blockDim.x + threadIdx.x; i < N_NODES * HID; i += stride)
        g_agg[i] = 0.0f;
    for (int i = blockIdx.x * blockDim.x + threadIdx.x; i < N_NODES * 3; i += stride)
        g_cagg[i] = 0.0f;
}

// ---------------- edge kernel: 4 edge-pairs per warp, persistent --------------
// feature pair layout (per pair, EPS floats):
//   slots 2k+q for k<64:   h[row] channel k, parity q
//   slots 128+2k'+q:       h[col] channel k' (k = 64+k')
//   slot 256+q:            radial
//   slots 258+2j+q (j<3):  diff component j
#define EPS 268
#define MPS 132
#define E_OFF_W1   0
#define E_OFF_W2   8256
#define E_OFF_CW1  12352
#define E_OFF_B1   16448
#define E_OFF_B2   16512
#define E_OFF_CB1  16576
#define E_OFF_CW2  16640
#define E_OFF_FEAT 16704
#define E_OFF_M    (E_OFF_FEAT + WARPS_CTA * 4 * EPS)     // 16704 + 17152 = 33856
#define E_SMEM_FLOATS (E_OFF_M + WARPS_CTA * 4 * MPS)     // 33856 + 8448  = 42304

__global__ __launch_bounds__(CTA_THREADS, 1) void edge_kernel(
    const int* __restrict__ row, const int* __restrict__ col,
    const float* __restrict__ W1, const float* __restrict__ B1,
    const float* __restrict__ W2, const float* __restrict__ B2,
    const float* __restrict__ CW1, const float* __restrict__ CB1,
    const float* __restrict__ CW2)
{
    extern __shared__ float s[];
    float* sW1  = s + E_OFF_W1;
    float* sW2  = s + E_OFF_W2;
    float* sCW1 = s + E_OFF_CW1;
    float* sB1  = s + E_OFF_B1;
    float* sB2  = s + E_OFF_B2;
    float* sCB1 = s + E_OFF_CB1;
    float* sCW2 = s + E_OFF_CW2;

    int tid = threadIdx.x;
    for (int i = tid; i < 8256; i += CTA_THREADS) sW1[i] = W1[i];
    for (int i = tid; i < 4096; i += CTA_THREADS) { sW2[i] = W2[i]; sCW1[i] = CW1[i]; }
    if (tid < 64) {
        sB1[tid] = B1[tid]; sB2[tid] = B2[tid];
        sCB1[tid] = CB1[tid]; sCW2[tid] = CW2[tid];
    }
    __syncthreads();

    int lane = tid & 31;
    int wid  = tid >> 5;
    float* fw = s + E_OFF_FEAT + wid * (4 * EPS);
    float* mw = s + E_OFF_M    + wid * (4 * MPS);

    float2 b1v  = ((const float2*)sB1)[lane];
    float2 b2v  = ((const float2*)sB2)[lane];
    float2 cb1v = ((const float2*)sCB1)[lane];
    float2 cw2v = ((const float2*)sCW2)[lane];

    for (int tile = blockIdx.x; tile < EDGE_TILES; tile += gridDim.x) {
        int ebase = tile * TILE_E + wid * EPW;
        int r[EPW];

        // ---- gather into pair-interleaved layout ----
        #pragma unroll
        for (int e = 0; e < EPW; e++) {
            int rr = __ldg(&row[ebase + e]);
            int cc = __ldg(&col[ebase + e]);
            r[e] = rr;
            float* fpq = fw + (e >> 1) * EPS + (e & 1);
            fpq[2 * lane]       = __ldg(&g_h[rr * HID + lane]);
            fpq[64 + 2 * lane]  = __ldg(&g_h[rr * HID + 32 + lane]);
            fpq[128 + 2 * lane] = __ldg(&g_h[cc * HID + lane]);
            fpq[192 + 2 * lane] = __ldg(&g_h[cc * HID + 32 + lane]);
            if (lane == 0) {
                float d0 = __ldg(&g_x[rr * 3 + 0]) - __ldg(&g_x[cc * 3 + 0]);
                float d1 = __ldg(&g_x[rr * 3 + 1]) - __ldg(&g_x[cc * 3 + 1]);
                float d2 = __ldg(&g_x[rr * 3 + 2]) - __ldg(&g_x[cc * 3 + 2]);
                fpq[256] = d0 * d0 + d1 * d1 + d2 * d2;
                fpq[258] = d0; fpq[260] = d1; fpq[262] = d2;
            }
        }
        __syncwarp();

        // ---- GEMM1: m1 = silu(feat @ W1 + b1), radial row folded into init ----
        ull acc[4][2];
        {
            float2 w128 = ((const float2*)(sW1 + 128 * 64))[lane];
            ull wr0 = splat2(w128.x), wr1 = splat2(w128.y);
            #pragma unroll
            for (int p = 0; p < 4; p++) {
                ull rad = *(const ull*)(fw + p * EPS + 256);
                acc[p][0] = splat2(b1v.x); ffma2(acc[p][0], rad, wr0);
                acc[p][1] = splat2(b1v.y); ffma2(acc[p][1], rad, wr1);
            }
        }
        gemm_pair<128, EPS>(acc, sW1, fw, lane);
        #pragma unroll
        for (int p = 0; p < 4; p++) {
            F2u a0, a1; a0.u = acc[p][0]; a1.u = acc[p][1];
            a0.f.x = silu(a0.f.x); a0.f.y = silu(a0.f.y);
            a1.f.x = silu(a1.f.x); a1.f.y = silu(a1.f.y);
            *(ulonglong2*)(mw + p * MPS + 4 * lane) = make_ulonglong2(a0.u, a1.u);
        }
        __syncwarp();

        // ---- GEMM2: m = silu(m1 @ W2 + b2) ----
        #pragma unroll
        for (int p = 0; p < 4; p++) { acc[p][0] = splat2(b2v.x); acc[p][1] = splat2(b2v.y); }
        gemm_pair<64, MPS>(acc, sW2, mw, lane);
        __syncwarp();   // all lanes done reading m1 before overwrite
        #pragma unroll
        for (int p = 0; p < 4; p++) {
            F2u a0, a1; a0.u = acc[p][0]; a1.u = acc[p][1];
            a0.f.x = silu(a0.f.x); a0.f.y = silu(a0.f.y);
            a1.f.x = silu(a1.f.x); a1.f.y = silu(a1.f.y);
            *(ulonglong2*)(mw + p * MPS + 4 * lane) = make_ulonglong2(a0.u, a1.u);
            atomicAdd(&g_agg[r[2 * p]     * HID + 2 * lane],     a0.f.x);
            atomicAdd(&g_agg[r[2 * p + 1] * HID + 2 * lane],     a0.f.y);
            atomicAdd(&g_agg[r[2 * p]     * HID + 2 * lane + 1], a1.f.x);
            atomicAdd(&g_agg[r[2 * p + 1] * HID + 2 * lane + 1], a1.f.y);
        }
        __syncwarp();

        // ---- GEMM3: cmid = silu(m @ CW1 + cb1); sc = cmid @ CW2 ----
        #pragma unroll
        for (int p = 0; p < 4; p++) { acc[p][0] = splat2(cb1v.x); acc[p][1] = splat2(cb1v.y); }
        gemm_pair<64, MPS>(acc, sCW1, mw, lane);
        #pragma unroll
        for (int p = 0; p < 4; p++) {
            F2u a0, a1; a0.u = acc[p][0]; a1.u = acc[p][1];
            float se = silu(a0.f.x) * cw2v.x + silu(a1.f.x) * cw2v.y;  // even edge
            float so = silu(a0.f.y) * cw2v.x + silu(a1.f.y) * cw2v.y;  // odd edge
            #pragma unroll
            for (int o = 16; o; o >>= 1) {
                se += __shfl_xor_sync(0xFFFFFFFFu, se, o);
                so += __shfl_xor_sync(0xFFFFFFFFu, so, o);
            }
            if (lane < 3) {
                float de = fw[p * EPS + 258 + 2 * lane];
                float dq = fw[p * EPS + 258 + 2 * lane + 1];
                atomicAdd(&g_cagg[r[2 * p]     * 3 + lane], de * se);
                atomicAdd(&g_cagg[r[2 * p + 1] * 3 + lane], dq * so);
            }
        }
        __syncwarp();   // before next tile reuses fw
    }
}

// ---------------- node kernel: 4 node-pairs per warp, persistent --------------
#define NPS 260
#define UPS 132
#define N_OFF_W1   0
#define N_OFF_W2   8192
#define N_OFF_B1   12288
#define N_OFF_B2   12352
#define N_OFF_FEAT 12416
#define N_OFF_U    (N_OFF_FEAT + WARPS_CTA * 4 * NPS)     // 12416 + 16640 = 29056
#define N_SMEM_FLOATS (N_OFF_U + WARPS_CTA * 4 * UPS)     // 29056 + 8448  = 37504

__global__ __launch_bounds__(CTA_THREADS, 1) void node_kernel(
    const float* __restrict__ W1, const float* __restrict__ B1,
    const float* __restrict__ W2, const float* __restrict__ B2)
{
    extern __shared__ float s[];
    float* sW1 = s + N_OFF_W1;
    float* sW2 = s + N_OFF_W2;
    float* sB1 = s + N_OFF_B1;
    float* sB2 = s + N_OFF_B2;

    int tid = threadIdx.x;
    for (int i = tid; i < 8192; i += CTA_THREADS) sW1[i] = W1[i];
    for (int i = tid; i < 4096; i += CTA_THREADS) sW2[i] = W2[i];
    if (tid < 64) { sB1[tid] = B1[tid]; sB2[tid] = B2[tid]; }
    __syncthreads();

    int lane = tid & 31;
    int wid  = tid >> 5;
    float* fw = s + N_OFF_FEAT + wid * (4 * NPS);
    float* uw = s + N_OFF_U    + wid * (4 * UPS);

    float2 b1v = ((const float2*)sB1)[lane];
    float2 b2v = ((const float2*)sB2)[lane];

    for (int tile = blockIdx.x; tile < NODE_TILES; tile += gridDim.x) {
        int nbase = tile * TILE_E + wid * EPW;

        #pragma unroll
        for (int e = 0; e < EPW; e++) {
            int n = nbase + e;
            if (n < N_NODES) {
                float* fpq = fw + (e >> 1) * NPS + (e & 1);
                fpq[2 * lane]       = g_h[n * HID + lane];
                fpq[64 + 2 * lane]  = g_h[n * HID + 32 + lane];
                fpq[128 + 2 * lane] = g_agg[n * HID + lane];
                fpq[192 + 2 * lane] = g_agg[n * HID + 32 + lane];
            }
        }
        __syncwarp();

        ull acc[4][2];
        #pragma unroll
        for (int p = 0; p < 4; p++) { acc[p][0] = splat2(b1v.x); acc[p][1] = splat2(b1v.y); }
        gemm_pair<128, NPS>(acc, sW1, fw, lane);
        #pragma unroll
        for (int p = 0; p < 4; p++) {
            F2u a0, a1; a0.u = acc[p][0]; a1.u = acc[p][1];
            a0.f.x = silu(a0.f.x); a0.f.y = silu(a0.f.y);
            a1.f.x = silu(a1.f.x); a1.f.y = silu(a1.f.y);
            *(ulonglong2*)(uw + p * UPS + 4 * lane) = make_ulonglong2(a0.u, a1.u);
        }
        __syncwarp();

        #pragma unroll
        for (int p = 0; p < 4; p++) { acc[p][0] = splat2(b2v.x); acc[p][1] = splat2(b2v.y); }
        gemm_pair<64, UPS>(acc, sW2, uw, lane);

        #pragma unroll
        for (int p = 0; p < 4; p++) {
            F2u a0, a1; a0.u = acc[p][0]; a1.u = acc[p][1];
            // h_old packed: {h_e0_c0, h_e1_c0, h_e0_c1, h_e1_c1}
            float4 hq = *(const float4*)(fw + p * NPS + 4 * lane);
            int n0 = nbase + 2 * p, n1 = n0 + 1;
            if (n0 < N_NODES) {
                ((float2*)(g_h + n0 * HID))[lane] =
                    make_float2(hq.x + a0.f.x, hq.z + a1.f.x);
                if (lane < 3) {
                    float cnt = g_cnt[n0];
                    if (cnt < 1.0f) cnt = 1.0f;
                    g_x[n0 * 3 + lane] += g_cagg[n0 * 3 + lane] / cnt;
                }
            }
            if (n1 < N_NODES) {
                ((float2*)(g_h + n1 * HID))[lane] =
                    make_float2(hq.y + a0.f.y, hq.w + a1.f.y);
                if (lane < 3) {
                    float cnt = g_cnt[n1];
                    if (cnt < 1.0f) cnt = 1.0f;
                    g_x[n1 * 3 + lane] += g_cagg[n1 * 3 + lane] / cnt;
                }
            }
        }
        __syncwarp();
    }
}

// ---------------- head: out = relu((h@EW+eb)@HW1+hb1)@HW2+hb2 -----------------
#define H_OFF_EW   0
#define H_OFF_HW1  4096
#define H_OFF_HW2  8192
#define H_OFF_EB   9472
#define H_OFF_HB1  9536
#define H_OFF_HB2  9600
#define H_OFF_FEAT 9620
#define H_SMEM_FLOATS 10132

__global__ __launch_bounds__(256) void head_kernel(
    const float* __restrict__ EW, const float* __restrict__ EB,
    const float* __restrict__ HW1, const float* __restrict__ HB1,
    const float* __restrict__ HW2, const float* __restrict__ HB2,
    float* __restrict__ out)
{
    extern __shared__ float s[];
    float* sEW  = s + H_OFF_EW;
    float* sHW1 = s + H_OFF_HW1;
    float* sHW2 = s + H_OFF_HW2;
    float* sEB  = s + H_OFF_EB;
    float* sHB1 = s + H_OFF_HB1;
    float* sHB2 = s + H_OFF_HB2;

    int tid = threadIdx.x;
    for (int i = tid; i < 4096; i += 256) { sEW[i] = EW[i]; sHW1[i] = HW1[i]; }
    for (int i = tid; i < 1280; i += 256) sHW2[i] = HW2[i];
    if (tid < 64) { sEB[tid] = EB[tid]; sHB1[tid] = HB1[tid]; }
    if (tid < 20) sHB2[tid] = HB2[tid];
    __syncthreads();

    int lane = tid & 31;
    int wloc = tid >> 5;
    float* fw = s + H_OFF_FEAT + wloc * 64;

    int warp   = (blockIdx.x * blockDim.x + tid) >> 5;
    int nwarps = (gridDim.x * blockDim.x) >> 5;

    for (int n = warp; n < N_NODES; n += nwarps) {
        float h0 = g_h[n * HID + lane], h1 = g_h[n * HID + 32 + lane];
        fw[lane] = h0; fw[32 + lane] = h1;
        __syncwarp();

        float t0 = sEB[lane], t1 = sEB[32 + lane];
        #pragma unroll 8
        for (int k = 0; k < 64; k++) {
            float f = fw[k];
            t0 = fmaf(f, sEW[k * 64 + lane], t0);
            t1 = fmaf(f, sEW[k * 64 + 32 + lane], t1);
        }
        __syncwarp();
        fw[lane] = t0; fw[32 + lane] = t1;
        __syncwarp();

        float r0 = sHB1[lane], r1 = sHB1[32 + lane];
        #pragma unroll 8
        for (int k = 0; k < 64; k++) {
            float f = fw[k];
            r0 = fmaf(f, sHW1[k * 64 + lane], r0);
            r1 = fmaf(f, sHW1[k * 64 + 32 + lane], r1);
        }
        r0 = fmaxf(r0, 0.0f); r1 = fmaxf(r1, 0.0f);
        __syncwarp();
        fw[lane] = r0; fw[32 + lane] = r1;
        __syncwarp();

        if (lane < OUT_NF) {
            float o = sHB2[lane];
            #pragma unroll 8
            for (int k = 0; k < 64; k++)
                o = fmaf(fw[k], sHW2[k * OUT_NF + lane], o);
            out[n * OUT_NF + lane] = o;
        }
        __syncwarp();
    }
}

// ---------------- launcher ----------------------------------------------------
extern "C" void kernel_launch(void* const* d_in, const int* in_sizes, int n_in,
                              void* d_out, int out_size) {
    const float* h_in      = (const float*)d_in[0];
    const float* x_in      = (const float*)d_in[1];
    const int*   edges     = (const int*)d_in[2];
    const float* emb_in_w  = (const float*)d_in[3];
    const float* emb_in_b  = (const float*)d_in[4];
    const float* emb_out_w = (const float*)d_in[5];
    const float* emb_out_b = (const float*)d_in[6];
    const float* edge_w1   = (const float*)d_in[7];
    const float* edge_b1   = (const float*)d_in[8];
    const float* edge_w2   = (const float*)d_in[9];
    const float* edge_b2   = (const float*)d_in[10];
    const float* node_w1   = (const float*)d_in[11];
    const float* node_b1   = (const float*)d_in[12];
    const float* node_w2   = (const float*)d_in[13];
    const float* node_b2   = (const float*)d_in[14];
    const float* coord_w1  = (const float*)d_in[15];
    const float* coord_b1  = (const float*)d_in[16];
    const float* coord_w2  = (const float*)d_in[17];
    const float* head_w1   = (const float*)d_in[18];
    const float* head_b1   = (const float*)d_in[19];
    const float* head_w2   = (const float*)d_in[20];
    const float* head_b2   = (const float*)d_in[21];
    float* out = (float*)d_out;

    cudaFuncSetAttribute(edge_kernel, cudaFuncAttributeMaxDynamicSharedMemorySize,
                         E_SMEM_FLOATS * sizeof(float));
    cudaFuncSetAttribute(node_kernel, cudaFuncAttributeMaxDynamicSharedMemorySize,
                         N_SMEM_FLOATS * sizeof(float));
    cudaFuncSetAttribute(head_kernel, cudaFuncAttributeMaxDynamicSharedMemorySize,
                         H_SMEM_FLOATS * sizeof(float));

    const int* row = edges;
    const int* col = edges + N_EDGES;

    init_kernel<<<(N_NODES * 3 + 255) / 256, 256>>>(x_in);
    embed_kernel<<<(N_NODES * HID + 255) / 256, 256>>>(h_in, emb_in_w, emb_in_b);
    count_kernel<<<(N_EDGES + 255) / 256, 256>>>(row);

    for (int l = 0; l < N_LAYERS; l++) {
        zero_kernel<<<2048, 256>>>();
        edge_kernel<<<GRID_PERSIST, CTA_THREADS, E_SMEM_FLOATS * sizeof(float)>>>(
            row, col,
            edge_w1 + l * (2 * HID + 1) * HID, edge_b1 + l * HID,
            edge_w2 + l * HID * HID, edge_b2 + l * HID,
            coord_w1 + l * HID * HID, coord_b1 + l * HID,
            coord_w2 + l * HID);
        node_kernel<<<GRID_PERSIST, CTA_THREADS, N_SMEM_FLOATS * sizeof(float)>>>(
            node_w1 + l * 2 * HID * HID, node_b1 + l * HID,
            node_w2 + l * HID * HID, node_b2 + l * HID);
    }

    head_kernel<<<6250, 256, H_SMEM_FLOATS * sizeof(float)>>>(
        emb_out_w, emb_out_b, head_w1, head_b1, head_w2, head_b2, out);
}